// round 2
// baseline (speedup 1.0000x reference)
#include <cuda_runtime.h>
#include <cuda_bf16.h>
#include <math.h>

// Problem constants
#define BATCH 32768
#define DD    256
#define UU    256
#define P0    128
#define P1    64
#define BU    (BATCH*UU)          // 8,388,608

// ---------------------------------------------------------------------------
// Device scratch (allocation-free rule: use __device__ globals)
// ---------------------------------------------------------------------------
__device__ float g_pre_c[4ULL * BATCH * UU];   // 4 gate pre-activations, click branch
__device__ float g_pre_v[4ULL * BATCH * UU];   // 4 gate pre-activations, conv branch
__device__ float g_t0[BU];                     // h_c @ W_schat_c
__device__ float g_t1[BU];                     // h_v @ W_schat_v
__device__ float g_t2[BU];                     // h_v @ W_svhat_v
__device__ float g_t3[BU];                     // h_c_n @ W_svhat_c
__device__ float g_schat[BU];                  // selected s_c_hat
__device__ float g_svhat[BU];                  // s_v_hat
__device__ float g_m0[BATCH * P0];             // MLP hidden0
__device__ float g_m1[BATCH * P1];             // MLP hidden1

// ---------------------------------------------------------------------------
// Classic 128x128 SGEMM, BK=16, 256 threads, 8x8 per thread.
// C[M,N] = A[M,K] @ W[K,N] (+ bias[N]) (+ Cin[M,N]), optional LeakyReLU(0.3).
// M assumed multiple of 128 (always 32768 here). N % 4 == 0, K % 16 == 0.
// ---------------------------------------------------------------------------
#define BM 128
#define BN 128
#define BK 16
#define TM 8
#define TN 8

__global__ __launch_bounds__(256) void sgemm_k(
    const float* __restrict__ A, const float* __restrict__ W,
    const float* __restrict__ bias, const float* __restrict__ Cin,
    float* __restrict__ C, int N, int K, int act)
{
    __shared__ float As[BK][BM];
    __shared__ float Bs[BK][BN];

    const int tid = threadIdx.x;
    const int m0  = blockIdx.y * BM;
    const int n0  = blockIdx.x * BN;
    const int tx  = tid & 15;
    const int ty  = tid >> 4;

    float acc[TM][TN];
#pragma unroll
    for (int i = 0; i < TM; i++)
#pragma unroll
        for (int j = 0; j < TN; j++) acc[i][j] = 0.f;

    for (int k0 = 0; k0 < K; k0 += BK) {
        // A tile: 128 rows x 16 cols = 512 float4, 2 per thread, store transposed
#pragma unroll
        for (int i = 0; i < 2; i++) {
            int f  = tid + i * 256;
            int ar = f >> 2;            // 0..127
            int ac = (f & 3) << 2;      // 0,4,8,12
            float4 v = *reinterpret_cast<const float4*>(
                &A[(size_t)(m0 + ar) * K + k0 + ac]);
            As[ac + 0][ar] = v.x;
            As[ac + 1][ar] = v.y;
            As[ac + 2][ar] = v.z;
            As[ac + 3][ar] = v.w;
        }
        // W tile: 16 rows x 128 cols = 512 float4, 2 per thread
#pragma unroll
        for (int i = 0; i < 2; i++) {
            int f   = tid + i * 256;
            int br  = f >> 5;           // 0..15
            int bc  = (f & 31) << 2;    // 0..124
            int col = n0 + bc;
            float4 v = make_float4(0.f, 0.f, 0.f, 0.f);
            if (col < N)
                v = *reinterpret_cast<const float4*>(
                    &W[(size_t)(k0 + br) * N + col]);
            *reinterpret_cast<float4*>(&Bs[br][bc]) = v;
        }
        __syncthreads();

#pragma unroll
        for (int k = 0; k < BK; k++) {
            float ra[TM], rb[TN];
#pragma unroll
            for (int i = 0; i < TM; i++) ra[i] = As[k][ty * TM + i];
#pragma unroll
            for (int j = 0; j < TN; j++) rb[j] = Bs[k][tx * TN + j];
#pragma unroll
            for (int i = 0; i < TM; i++)
#pragma unroll
                for (int j = 0; j < TN; j++)
                    acc[i][j] = fmaf(ra[i], rb[j], acc[i][j]);
        }
        __syncthreads();
    }

    // Epilogue
#pragma unroll
    for (int i = 0; i < TM; i++) {
        int row = m0 + ty * TM + i;
#pragma unroll
        for (int j = 0; j < TN; j++) {
            int col = n0 + tx * TN + j;
            if (col < N) {
                float v = acc[i][j];
                if (bias) v += bias[col];
                if (Cin)  v += Cin[(size_t)row * N + col];
                if (act == 1) v = (v > 0.f) ? v : 0.3f * v;
                C[(size_t)row * N + col] = v;
            }
        }
    }
}

// ---------------------------------------------------------------------------
// Elementwise kernels
// ---------------------------------------------------------------------------
__device__ __forceinline__ float sigm(float x) { return 1.f / (1.f + expf(-x)); }

// s_c_hat = gp ? (h_v@W_schat_v) : (h_c@W_schat_c)
__global__ void select_schat_k(const int* __restrict__ g_prev,
                               const float* __restrict__ t0,
                               const float* __restrict__ t1,
                               float* __restrict__ schat)
{
    int i = blockIdx.x * blockDim.x + threadIdx.x;
    if (i < BU) schat[i] = (g_prev[i] > 0) ? t1[i] : t0[i];
}

// click-branch gates -> s_c_n, h_c_n
__global__ void gates_c_k(const float* __restrict__ pre,
                          const float* __restrict__ s_c,
                          const int*   __restrict__ g_prev,
                          float* __restrict__ out_scn,
                          float* __restrict__ out_hcn)
{
    int i = blockIdx.x * blockDim.x + threadIdx.x;
    if (i >= BU) return;
    float f  = sigm(pre[0ULL * BU + i]);
    float ii = sigm(pre[1ULL * BU + i]);
    float o  = sigm(pre[2ULL * BU + i]);
    float g  = tanhf(pre[3ULL * BU + i]);
    bool  gp = g_prev[i] > 0;
    float scn = ii * g + (gp ? 0.f : f * s_c[i]);
    out_scn[i] = scn;
    out_hcn[i] = o * tanhf(scn);
}

// s_v_hat = t2 + (gm ? t3 : 0)
__global__ void svhat_k(const float* __restrict__ click,
                        const float* __restrict__ t2,
                        const float* __restrict__ t3,
                        float* __restrict__ svhat)
{
    int i = blockIdx.x * blockDim.x + threadIdx.x;
    if (i >= BU) return;
    int  b  = i / UU;
    bool gm = click[b] >= 0.5f;
    svhat[i] = t2[i] + (gm ? t3[i] : 0.f);
}

// conversion-branch gates -> s_v_n, h_v_n, g_new
__global__ void gates_v_k(const float* __restrict__ pre,
                          const float* __restrict__ s_v,
                          const float* __restrict__ h_v,
                          const float* __restrict__ click,
                          float* __restrict__ out_svn,
                          float* __restrict__ out_hvn,
                          float* __restrict__ out_gnew)
{
    int i = blockIdx.x * blockDim.x + threadIdx.x;
    if (i >= BU) return;
    int  b  = i / UU;
    bool gm = click[b] >= 0.5f;
    float f  = sigm(pre[0ULL * BU + i]);
    float ii = sigm(pre[1ULL * BU + i]);
    float o  = sigm(pre[2ULL * BU + i]);
    float g  = tanhf(pre[3ULL * BU + i]);
    float sv = s_v[i];
    float svn = gm ? (f * sv + ii * g) : sv;
    out_svn[i]  = svn;
    out_hvn[i]  = gm ? (o * tanhf(svn)) : h_v[i];
    out_gnew[i] = gm ? 1.f : 0.f;
}

// Final MLP layer: out[b] = sigmoid(dot(M1[b,:64], Wf) + bf) (* scale[b])
// one warp per row
__global__ void mlp_final_k(const float* __restrict__ M1,
                            const float* __restrict__ Wf,
                            const float* __restrict__ bf,
                            const float* __restrict__ scale,  // nullable
                            float* __restrict__ out)
{
    int warp = (blockIdx.x * blockDim.x + threadIdx.x) >> 5;
    int lane = threadIdx.x & 31;
    if (warp >= BATCH) return;
    const float* r = M1 + (size_t)warp * P1;
    float s = r[lane] * Wf[lane] + r[lane + 32] * Wf[lane + 32];
#pragma unroll
    for (int o = 16; o; o >>= 1) s += __shfl_down_sync(0xffffffffu, s, o);
    if (lane == 0) {
        float v = sigm(s + bf[0]);
        if (scale) v *= scale[warp];
        out[warp] = v;
    }
}

// ---------------------------------------------------------------------------
// Launcher
// ---------------------------------------------------------------------------
extern "C" void kernel_launch(void* const* d_in, const int* in_sizes, int n_in,
                              void* d_out, int out_size)
{
    (void)in_sizes; (void)n_in; (void)out_size;

    const float* x        = (const float*)d_in[0];
    const float* click    = (const float*)d_in[1];
    const float* h_c      = (const float*)d_in[2];
    const float* h_v      = (const float*)d_in[3];
    const float* s_c      = (const float*)d_in[4];
    const float* s_v      = (const float*)d_in[5];
    const int*   g_prev   = (const int*)  d_in[6];
    const float* Wx_c     = (const float*)d_in[7];
    const float* bx_c     = (const float*)d_in[8];
    const float* Wh_c     = (const float*)d_in[9];
    const float* Wx_v     = (const float*)d_in[10];
    const float* bx_v     = (const float*)d_in[11];
    const float* Wh_v     = (const float*)d_in[12];
    const float* W_schat_c= (const float*)d_in[13];
    const float* W_schat_v= (const float*)d_in[14];
    const float* W_svhat_v= (const float*)d_in[15];
    const float* W_svhat_c= (const float*)d_in[16];
    const float* Wpc0     = (const float*)d_in[17];
    const float* bpc0     = (const float*)d_in[18];
    const float* Wpc1     = (const float*)d_in[19];
    const float* bpc1     = (const float*)d_in[20];
    const float* Wfcc     = (const float*)d_in[21];
    const float* bfcc     = (const float*)d_in[22];
    const float* Wpv0     = (const float*)d_in[23];
    const float* bpv0     = (const float*)d_in[24];
    const float* Wpv1     = (const float*)d_in[25];
    const float* bpv1     = (const float*)d_in[26];
    const float* Wfcv     = (const float*)d_in[27];
    const float* bfcv     = (const float*)d_in[28];

    float *pre_c, *pre_v, *t0, *t1, *t2, *t3, *schat, *svhat, *m0, *m1;
    cudaGetSymbolAddress((void**)&pre_c, g_pre_c);
    cudaGetSymbolAddress((void**)&pre_v, g_pre_v);
    cudaGetSymbolAddress((void**)&t0,    g_t0);
    cudaGetSymbolAddress((void**)&t1,    g_t1);
    cudaGetSymbolAddress((void**)&t2,    g_t2);
    cudaGetSymbolAddress((void**)&t3,    g_t3);
    cudaGetSymbolAddress((void**)&schat, g_schat);
    cudaGetSymbolAddress((void**)&svhat, g_svhat);
    cudaGetSymbolAddress((void**)&m0,    g_m0);
    cudaGetSymbolAddress((void**)&m1,    g_m1);

    float* out     = (float*)d_out;
    float* o_hcp   = out;                       // [B,1]
    float* o_hvp   = out + BATCH;               // [B,1]
    float* o_hcn   = out + 2 * BATCH;           // [B,U]
    float* o_hvn   = o_hcn + (size_t)BU;        // [B,U]
    float* o_scn   = o_hvn + (size_t)BU;        // [B,U]
    float* o_svn   = o_scn + (size_t)BU;        // [B,U]
    float* o_gnew  = o_svn + (size_t)BU;        // [B,U]

    dim3 blk(256);
    dim3 g256(UU / BN, BATCH / BM);      // N=256 -> (2, 256)
    dim3 g128(1, BATCH / BM);            // N=128
    dim3 g64 (1, BATCH / BM);            // N=64
    int  ewGrid = (BU + 255) / 256;

    // ---- Stage A: x-gates pre-activations + independent h-projections ----
    for (int k = 0; k < 4; k++) {
        sgemm_k<<<g256, blk>>>(x, Wx_c + (size_t)k * DD * UU, bx_c + k * UU,
                               nullptr, pre_c + (size_t)k * BU, UU, DD, 0);
        sgemm_k<<<g256, blk>>>(x, Wx_v + (size_t)k * DD * UU, bx_v + k * UU,
                               nullptr, pre_v + (size_t)k * BU, UU, DD, 0);
    }
    sgemm_k<<<g256, blk>>>(h_c, W_schat_c, nullptr, nullptr, t0, UU, UU, 0);
    sgemm_k<<<g256, blk>>>(h_v, W_schat_v, nullptr, nullptr, t1, UU, UU, 0);
    sgemm_k<<<g256, blk>>>(h_v, W_svhat_v, nullptr, nullptr, t2, UU, UU, 0);

    // ---- Stage B: select s_c_hat ----
    select_schat_k<<<ewGrid, blk>>>(g_prev, t0, t1, schat);

    // ---- Stage C: h-gates for click branch (accumulate into pre_c) ----
    for (int k = 0; k < 4; k++)
        sgemm_k<<<g256, blk>>>(schat, Wh_c + (size_t)k * UU * UU, nullptr,
                               pre_c + (size_t)k * BU, pre_c + (size_t)k * BU,
                               UU, UU, 0);

    // ---- Stage D: click gates -> s_c_n, h_c_n ----
    gates_c_k<<<ewGrid, blk>>>(pre_c, s_c, g_prev, o_scn, o_hcn);

    // ---- Stage E: click MLP ----
    sgemm_k<<<g128, blk>>>(o_hcn, Wpc0, bpc0, nullptr, m0, P0, UU, 1);
    sgemm_k<<<g64,  blk>>>(m0,    Wpc1, bpc1, nullptr, m1, P1, P0, 1);
    mlp_final_k<<<(BATCH * 32 + 255) / 256, blk>>>(m1, Wfcc, bfcc, nullptr, o_hcp);

    // ---- Stage F: s_v_hat ----
    sgemm_k<<<g256, blk>>>(o_hcn, W_svhat_c, nullptr, nullptr, t3, UU, UU, 0);
    svhat_k<<<ewGrid, blk>>>(click, t2, t3, svhat);

    // ---- Stage G: h-gates for conversion branch ----
    for (int k = 0; k < 4; k++)
        sgemm_k<<<g256, blk>>>(svhat, Wh_v + (size_t)k * UU * UU, nullptr,
                               pre_v + (size_t)k * BU, pre_v + (size_t)k * BU,
                               UU, UU, 0);

    // ---- Stage H: conversion gates -> s_v_n, h_v_n, g_new ----
    gates_v_k<<<ewGrid, blk>>>(pre_v, s_v, h_v, click, o_svn, o_hvn, o_gnew);

    // ---- Stage I: conversion MLP (scaled by h_c_p) ----
    sgemm_k<<<g128, blk>>>(o_hvn, Wpv0, bpv0, nullptr, m0, P0, UU, 1);
    sgemm_k<<<g64,  blk>>>(m0,    Wpv1, bpv1, nullptr, m1, P1, P0, 1);
    mlp_final_k<<<(BATCH * 32 + 255) / 256, blk>>>(m1, Wfcv, bfcv, o_hcp, o_hvp);
}

// round 3
// speedup vs baseline: 1.0010x; 1.0010x over previous
#include <cuda_runtime.h>
#include <cuda_bf16.h>
#include <math.h>

// Problem constants
#define BATCH 32768
#define DD    256
#define UU    256
#define P0    128
#define P1    64
#define BU    (BATCH*UU)          // 8,388,608

// ---------------------------------------------------------------------------
// Device scratch (allocation-free rule: use __device__ globals)
// ---------------------------------------------------------------------------
__device__ float g_pre_c[4ULL * BATCH * UU];   // 4 gate pre-activations, click branch
__device__ float g_pre_v[4ULL * BATCH * UU];   // 4 gate pre-activations, conv branch
__device__ float g_t0[BU];                     // h_c @ W_schat_c
__device__ float g_t1[BU];                     // h_v @ W_schat_v
__device__ float g_t2[BU];                     // h_v @ W_svhat_v
__device__ float g_t3[BU];                     // h_c_n @ W_svhat_c
__device__ float g_schat[BU];                  // selected s_c_hat
__device__ float g_svhat[BU];                  // s_v_hat
__device__ float g_m0[BATCH * P0];             // MLP hidden0
__device__ float g_m1[BATCH * P1];             // MLP hidden1

// ---------------------------------------------------------------------------
// Classic 128x128 SGEMM, BK=16, 256 threads, 8x8 per thread.
// C[M,N] = A[M,K] @ W[K,N] (+ bias[N]) (+ Cin[M,N]), optional LeakyReLU(0.3).
// M assumed multiple of 128 (always 32768 here). N % 4 == 0, K % 16 == 0.
// ---------------------------------------------------------------------------
#define BM 128
#define BN 128
#define BK 16
#define TM 8
#define TN 8

__global__ __launch_bounds__(256) void sgemm_k(
    const float* __restrict__ A, const float* __restrict__ W,
    const float* __restrict__ bias, const float* __restrict__ Cin,
    float* __restrict__ C, int N, int K, int act)
{
    __shared__ float As[BK][BM];
    __shared__ float Bs[BK][BN];

    const int tid = threadIdx.x;
    const int m0  = blockIdx.y * BM;
    const int n0  = blockIdx.x * BN;
    const int tx  = tid & 15;
    const int ty  = tid >> 4;

    float acc[TM][TN];
#pragma unroll
    for (int i = 0; i < TM; i++)
#pragma unroll
        for (int j = 0; j < TN; j++) acc[i][j] = 0.f;

    for (int k0 = 0; k0 < K; k0 += BK) {
        // A tile: 128 rows x 16 cols = 512 float4, 2 per thread, store transposed
#pragma unroll
        for (int i = 0; i < 2; i++) {
            int f  = tid + i * 256;
            int ar = f >> 2;            // 0..127
            int ac = (f & 3) << 2;      // 0,4,8,12
            float4 v = *reinterpret_cast<const float4*>(
                &A[(size_t)(m0 + ar) * K + k0 + ac]);
            As[ac + 0][ar] = v.x;
            As[ac + 1][ar] = v.y;
            As[ac + 2][ar] = v.z;
            As[ac + 3][ar] = v.w;
        }
        // W tile: 16 rows x 128 cols = 512 float4, 2 per thread
#pragma unroll
        for (int i = 0; i < 2; i++) {
            int f   = tid + i * 256;
            int br  = f >> 5;           // 0..15
            int bc  = (f & 31) << 2;    // 0..124
            int col = n0 + bc;
            float4 v = make_float4(0.f, 0.f, 0.f, 0.f);
            if (col < N)
                v = *reinterpret_cast<const float4*>(
                    &W[(size_t)(k0 + br) * N + col]);
            *reinterpret_cast<float4*>(&Bs[br][bc]) = v;
        }
        __syncthreads();

#pragma unroll
        for (int k = 0; k < BK; k++) {
            float ra[TM], rb[TN];
#pragma unroll
            for (int i = 0; i < TM; i++) ra[i] = As[k][ty * TM + i];
#pragma unroll
            for (int j = 0; j < TN; j++) rb[j] = Bs[k][tx * TN + j];
#pragma unroll
            for (int i = 0; i < TM; i++)
#pragma unroll
                for (int j = 0; j < TN; j++)
                    acc[i][j] = fmaf(ra[i], rb[j], acc[i][j]);
        }
        __syncthreads();
    }

    // Epilogue
#pragma unroll
    for (int i = 0; i < TM; i++) {
        int row = m0 + ty * TM + i;
#pragma unroll
        for (int j = 0; j < TN; j++) {
            int col = n0 + tx * TN + j;
            if (col < N) {
                float v = acc[i][j];
                if (bias) v += bias[col];
                if (Cin)  v += Cin[(size_t)row * N + col];
                if (act == 1) v = (v > 0.f) ? v : 0.3f * v;
                C[(size_t)row * N + col] = v;
            }
        }
    }
}

// ---------------------------------------------------------------------------
// Elementwise kernels
// ---------------------------------------------------------------------------
__device__ __forceinline__ float sigm(float x) { return 1.f / (1.f + expf(-x)); }

// s_c_hat = gp ? (h_v@W_schat_v) : (h_c@W_schat_c)
__global__ void select_schat_k(const int* __restrict__ g_prev,
                               const float* __restrict__ t0,
                               const float* __restrict__ t1,
                               float* __restrict__ schat)
{
    int i = blockIdx.x * blockDim.x + threadIdx.x;
    if (i < BU) schat[i] = (g_prev[i] > 0) ? t1[i] : t0[i];
}

// click-branch gates -> s_c_n, h_c_n
__global__ void gates_c_k(const float* __restrict__ pre,
                          const float* __restrict__ s_c,
                          const int*   __restrict__ g_prev,
                          float* __restrict__ out_scn,
                          float* __restrict__ out_hcn)
{
    int i = blockIdx.x * blockDim.x + threadIdx.x;
    if (i >= BU) return;
    float f  = sigm(pre[0ULL * BU + i]);
    float ii = sigm(pre[1ULL * BU + i]);
    float o  = sigm(pre[2ULL * BU + i]);
    float g  = tanhf(pre[3ULL * BU + i]);
    bool  gp = g_prev[i] > 0;
    float scn = ii * g + (gp ? 0.f : f * s_c[i]);
    out_scn[i] = scn;
    out_hcn[i] = o * tanhf(scn);
}

// s_v_hat = t2 + (gm ? t3 : 0)
__global__ void svhat_k(const float* __restrict__ click,
                        const float* __restrict__ t2,
                        const float* __restrict__ t3,
                        float* __restrict__ svhat)
{
    int i = blockIdx.x * blockDim.x + threadIdx.x;
    if (i >= BU) return;
    int  b  = i / UU;
    bool gm = click[b] >= 0.5f;
    svhat[i] = t2[i] + (gm ? t3[i] : 0.f);
}

// conversion-branch gates -> s_v_n, h_v_n, g_new
__global__ void gates_v_k(const float* __restrict__ pre,
                          const float* __restrict__ s_v,
                          const float* __restrict__ h_v,
                          const float* __restrict__ click,
                          float* __restrict__ out_svn,
                          float* __restrict__ out_hvn,
                          float* __restrict__ out_gnew)
{
    int i = blockIdx.x * blockDim.x + threadIdx.x;
    if (i >= BU) return;
    int  b  = i / UU;
    bool gm = click[b] >= 0.5f;
    float f  = sigm(pre[0ULL * BU + i]);
    float ii = sigm(pre[1ULL * BU + i]);
    float o  = sigm(pre[2ULL * BU + i]);
    float g  = tanhf(pre[3ULL * BU + i]);
    float sv = s_v[i];
    float svn = gm ? (f * sv + ii * g) : sv;
    out_svn[i]  = svn;
    out_hvn[i]  = gm ? (o * tanhf(svn)) : h_v[i];
    out_gnew[i] = gm ? 1.f : 0.f;
}

// Final MLP layer: out[b] = sigmoid(dot(M1[b,:64], Wf) + bf) (* scale[b])
// one warp per row
__global__ void mlp_final_k(const float* __restrict__ M1,
                            const float* __restrict__ Wf,
                            const float* __restrict__ bf,
                            const float* __restrict__ scale,  // nullable
                            float* __restrict__ out)
{
    int warp = (blockIdx.x * blockDim.x + threadIdx.x) >> 5;
    int lane = threadIdx.x & 31;
    if (warp >= BATCH) return;
    const float* r = M1 + (size_t)warp * P1;
    float s = r[lane] * Wf[lane] + r[lane + 32] * Wf[lane + 32];
#pragma unroll
    for (int o = 16; o; o >>= 1) s += __shfl_down_sync(0xffffffffu, s, o);
    if (lane == 0) {
        float v = sigm(s + bf[0]);
        if (scale) v *= scale[warp];
        out[warp] = v;
    }
}

// ---------------------------------------------------------------------------
// Launcher
// ---------------------------------------------------------------------------
extern "C" void kernel_launch(void* const* d_in, const int* in_sizes, int n_in,
                              void* d_out, int out_size)
{
    (void)in_sizes; (void)n_in; (void)out_size;

    const float* x        = (const float*)d_in[0];
    const float* click    = (const float*)d_in[1];
    const float* h_c      = (const float*)d_in[2];
    const float* h_v      = (const float*)d_in[3];
    const float* s_c      = (const float*)d_in[4];
    const float* s_v      = (const float*)d_in[5];
    const int*   g_prev   = (const int*)  d_in[6];
    const float* Wx_c     = (const float*)d_in[7];
    const float* bx_c     = (const float*)d_in[8];
    const float* Wh_c     = (const float*)d_in[9];
    const float* Wx_v     = (const float*)d_in[10];
    const float* bx_v     = (const float*)d_in[11];
    const float* Wh_v     = (const float*)d_in[12];
    const float* W_schat_c= (const float*)d_in[13];
    const float* W_schat_v= (const float*)d_in[14];
    const float* W_svhat_v= (const float*)d_in[15];
    const float* W_svhat_c= (const float*)d_in[16];
    const float* Wpc0     = (const float*)d_in[17];
    const float* bpc0     = (const float*)d_in[18];
    const float* Wpc1     = (const float*)d_in[19];
    const float* bpc1     = (const float*)d_in[20];
    const float* Wfcc     = (const float*)d_in[21];
    const float* bfcc     = (const float*)d_in[22];
    const float* Wpv0     = (const float*)d_in[23];
    const float* bpv0     = (const float*)d_in[24];
    const float* Wpv1     = (const float*)d_in[25];
    const float* bpv1     = (const float*)d_in[26];
    const float* Wfcv     = (const float*)d_in[27];
    const float* bfcv     = (const float*)d_in[28];

    float *pre_c, *pre_v, *t0, *t1, *t2, *t3, *schat, *svhat, *m0, *m1;
    cudaGetSymbolAddress((void**)&pre_c, g_pre_c);
    cudaGetSymbolAddress((void**)&pre_v, g_pre_v);
    cudaGetSymbolAddress((void**)&t0,    g_t0);
    cudaGetSymbolAddress((void**)&t1,    g_t1);
    cudaGetSymbolAddress((void**)&t2,    g_t2);
    cudaGetSymbolAddress((void**)&t3,    g_t3);
    cudaGetSymbolAddress((void**)&schat, g_schat);
    cudaGetSymbolAddress((void**)&svhat, g_svhat);
    cudaGetSymbolAddress((void**)&m0,    g_m0);
    cudaGetSymbolAddress((void**)&m1,    g_m1);

    float* out     = (float*)d_out;
    float* o_hcp   = out;                       // [B,1]
    float* o_hvp   = out + BATCH;               // [B,1]
    float* o_hcn   = out + 2 * BATCH;           // [B,U]
    float* o_hvn   = o_hcn + (size_t)BU;        // [B,U]
    float* o_scn   = o_hvn + (size_t)BU;        // [B,U]
    float* o_svn   = o_scn + (size_t)BU;        // [B,U]
    float* o_gnew  = o_svn + (size_t)BU;        // [B,U]

    dim3 blk(256);
    dim3 g256(UU / BN, BATCH / BM);      // N=256 -> (2, 256)
    dim3 g128(1, BATCH / BM);            // N=128
    dim3 g64 (1, BATCH / BM);            // N=64
    int  ewGrid = (BU + 255) / 256;

    // ---- Stage A: x-gates pre-activations + independent h-projections ----
    for (int k = 0; k < 4; k++) {
        sgemm_k<<<g256, blk>>>(x, Wx_c + (size_t)k * DD * UU, bx_c + k * UU,
                               nullptr, pre_c + (size_t)k * BU, UU, DD, 0);
        sgemm_k<<<g256, blk>>>(x, Wx_v + (size_t)k * DD * UU, bx_v + k * UU,
                               nullptr, pre_v + (size_t)k * BU, UU, DD, 0);
    }
    sgemm_k<<<g256, blk>>>(h_c, W_schat_c, nullptr, nullptr, t0, UU, UU, 0);
    sgemm_k<<<g256, blk>>>(h_v, W_schat_v, nullptr, nullptr, t1, UU, UU, 0);
    sgemm_k<<<g256, blk>>>(h_v, W_svhat_v, nullptr, nullptr, t2, UU, UU, 0);

    // ---- Stage B: select s_c_hat ----
    select_schat_k<<<ewGrid, blk>>>(g_prev, t0, t1, schat);

    // ---- Stage C: h-gates for click branch (accumulate into pre_c) ----
    for (int k = 0; k < 4; k++)
        sgemm_k<<<g256, blk>>>(schat, Wh_c + (size_t)k * UU * UU, nullptr,
                               pre_c + (size_t)k * BU, pre_c + (size_t)k * BU,
                               UU, UU, 0);

    // ---- Stage D: click gates -> s_c_n, h_c_n ----
    gates_c_k<<<ewGrid, blk>>>(pre_c, s_c, g_prev, o_scn, o_hcn);

    // ---- Stage E: click MLP ----
    sgemm_k<<<g128, blk>>>(o_hcn, Wpc0, bpc0, nullptr, m0, P0, UU, 1);
    sgemm_k<<<g64,  blk>>>(m0,    Wpc1, bpc1, nullptr, m1, P1, P0, 1);
    mlp_final_k<<<(BATCH * 32 + 255) / 256, blk>>>(m1, Wfcc, bfcc, nullptr, o_hcp);

    // ---- Stage F: s_v_hat ----
    sgemm_k<<<g256, blk>>>(o_hcn, W_svhat_c, nullptr, nullptr, t3, UU, UU, 0);
    svhat_k<<<ewGrid, blk>>>(click, t2, t3, svhat);

    // ---- Stage G: h-gates for conversion branch ----
    for (int k = 0; k < 4; k++)
        sgemm_k<<<g256, blk>>>(svhat, Wh_v + (size_t)k * UU * UU, nullptr,
                               pre_v + (size_t)k * BU, pre_v + (size_t)k * BU,
                               UU, UU, 0);

    // ---- Stage H: conversion gates -> s_v_n, h_v_n, g_new ----
    gates_v_k<<<ewGrid, blk>>>(pre_v, s_v, h_v, click, o_svn, o_hvn, o_gnew);

    // ---- Stage I: conversion MLP (scaled by h_c_p) ----
    sgemm_k<<<g128, blk>>>(o_hvn, Wpv0, bpv0, nullptr, m0, P0, UU, 1);
    sgemm_k<<<g64,  blk>>>(m0,    Wpv1, bpv1, nullptr, m1, P1, P0, 1);
    mlp_final_k<<<(BATCH * 32 + 255) / 256, blk>>>(m1, Wfcv, bfcv, o_hcp, o_hvp);
}

// round 4
// speedup vs baseline: 1.0028x; 1.0018x over previous
#include <cuda_runtime.h>
#include <cuda_bf16.h>
#include <math.h>

// Problem constants
#define BATCH 32768
#define DD    256
#define UU    256
#define P0    128
#define P1    64
#define BU    (BATCH*UU)          // 8,388,608

// ---------------------------------------------------------------------------
// Device scratch (allocation-free rule: use __device__ globals)
// ---------------------------------------------------------------------------
__device__ float g_pre_c[4ULL * BATCH * UU];   // 4 gate pre-activations, click branch
__device__ float g_pre_v[4ULL * BATCH * UU];   // 4 gate pre-activations, conv branch
__device__ float g_t0[BU];                     // h_c @ W_schat_c
__device__ float g_t1[BU];                     // h_v @ W_schat_v
__device__ float g_t2[BU];                     // h_v @ W_svhat_v
__device__ float g_t3[BU];                     // h_c_n @ W_svhat_c
__device__ float g_schat[BU];                  // selected s_c_hat
__device__ float g_svhat[BU];                  // s_v_hat
__device__ float g_m0[BATCH * P0];             // MLP hidden0
__device__ float g_m1[BATCH * P1];             // MLP hidden1

// ---------------------------------------------------------------------------
// Classic 128x128 SGEMM, BK=16, 256 threads, 8x8 per thread.
// C[M,N] = A[M,K] @ W[K,N] (+ bias[N]) (+ Cin[M,N]), optional LeakyReLU(0.3).
// M assumed multiple of 128 (always 32768 here). N % 4 == 0, K % 16 == 0.
// ---------------------------------------------------------------------------
#define BM 128
#define BN 128
#define BK 16
#define TM 8
#define TN 8

__global__ __launch_bounds__(256) void sgemm_k(
    const float* __restrict__ A, const float* __restrict__ W,
    const float* __restrict__ bias, const float* __restrict__ Cin,
    float* __restrict__ C, int N, int K, int act)
{
    __shared__ float As[BK][BM];
    __shared__ float Bs[BK][BN];

    const int tid = threadIdx.x;
    const int m0  = blockIdx.y * BM;
    const int n0  = blockIdx.x * BN;
    const int tx  = tid & 15;
    const int ty  = tid >> 4;

    float acc[TM][TN];
#pragma unroll
    for (int i = 0; i < TM; i++)
#pragma unroll
        for (int j = 0; j < TN; j++) acc[i][j] = 0.f;

    for (int k0 = 0; k0 < K; k0 += BK) {
        // A tile: 128 rows x 16 cols = 512 float4, 2 per thread, store transposed
#pragma unroll
        for (int i = 0; i < 2; i++) {
            int f  = tid + i * 256;
            int ar = f >> 2;            // 0..127
            int ac = (f & 3) << 2;      // 0,4,8,12
            float4 v = *reinterpret_cast<const float4*>(
                &A[(size_t)(m0 + ar) * K + k0 + ac]);
            As[ac + 0][ar] = v.x;
            As[ac + 1][ar] = v.y;
            As[ac + 2][ar] = v.z;
            As[ac + 3][ar] = v.w;
        }
        // W tile: 16 rows x 128 cols = 512 float4, 2 per thread
#pragma unroll
        for (int i = 0; i < 2; i++) {
            int f   = tid + i * 256;
            int br  = f >> 5;           // 0..15
            int bc  = (f & 31) << 2;    // 0..124
            int col = n0 + bc;
            float4 v = make_float4(0.f, 0.f, 0.f, 0.f);
            if (col < N)
                v = *reinterpret_cast<const float4*>(
                    &W[(size_t)(k0 + br) * N + col]);
            *reinterpret_cast<float4*>(&Bs[br][bc]) = v;
        }
        __syncthreads();

#pragma unroll
        for (int k = 0; k < BK; k++) {
            float ra[TM], rb[TN];
#pragma unroll
            for (int i = 0; i < TM; i++) ra[i] = As[k][ty * TM + i];
#pragma unroll
            for (int j = 0; j < TN; j++) rb[j] = Bs[k][tx * TN + j];
#pragma unroll
            for (int i = 0; i < TM; i++)
#pragma unroll
                for (int j = 0; j < TN; j++)
                    acc[i][j] = fmaf(ra[i], rb[j], acc[i][j]);
        }
        __syncthreads();
    }

    // Epilogue
#pragma unroll
    for (int i = 0; i < TM; i++) {
        int row = m0 + ty * TM + i;
#pragma unroll
        for (int j = 0; j < TN; j++) {
            int col = n0 + tx * TN + j;
            if (col < N) {
                float v = acc[i][j];
                if (bias) v += bias[col];
                if (Cin)  v += Cin[(size_t)row * N + col];
                if (act == 1) v = (v > 0.f) ? v : 0.3f * v;
                C[(size_t)row * N + col] = v;
            }
        }
    }
}

// ---------------------------------------------------------------------------
// Elementwise kernels
// ---------------------------------------------------------------------------
__device__ __forceinline__ float sigm(float x) { return 1.f / (1.f + expf(-x)); }

// s_c_hat = gp ? (h_v@W_schat_v) : (h_c@W_schat_c)
__global__ void select_schat_k(const int* __restrict__ g_prev,
                               const float* __restrict__ t0,
                               const float* __restrict__ t1,
                               float* __restrict__ schat)
{
    int i = blockIdx.x * blockDim.x + threadIdx.x;
    if (i < BU) schat[i] = (g_prev[i] > 0) ? t1[i] : t0[i];
}

// click-branch gates -> s_c_n, h_c_n
__global__ void gates_c_k(const float* __restrict__ pre,
                          const float* __restrict__ s_c,
                          const int*   __restrict__ g_prev,
                          float* __restrict__ out_scn,
                          float* __restrict__ out_hcn)
{
    int i = blockIdx.x * blockDim.x + threadIdx.x;
    if (i >= BU) return;
    float f  = sigm(pre[0ULL * BU + i]);
    float ii = sigm(pre[1ULL * BU + i]);
    float o  = sigm(pre[2ULL * BU + i]);
    float g  = tanhf(pre[3ULL * BU + i]);
    bool  gp = g_prev[i] > 0;
    float scn = ii * g + (gp ? 0.f : f * s_c[i]);
    out_scn[i] = scn;
    out_hcn[i] = o * tanhf(scn);
}

// s_v_hat = t2 + (gm ? t3 : 0)
__global__ void svhat_k(const float* __restrict__ click,
                        const float* __restrict__ t2,
                        const float* __restrict__ t3,
                        float* __restrict__ svhat)
{
    int i = blockIdx.x * blockDim.x + threadIdx.x;
    if (i >= BU) return;
    int  b  = i / UU;
    bool gm = click[b] >= 0.5f;
    svhat[i] = t2[i] + (gm ? t3[i] : 0.f);
}

// conversion-branch gates -> s_v_n, h_v_n, g_new
__global__ void gates_v_k(const float* __restrict__ pre,
                          const float* __restrict__ s_v,
                          const float* __restrict__ h_v,
                          const float* __restrict__ click,
                          float* __restrict__ out_svn,
                          float* __restrict__ out_hvn,
                          float* __restrict__ out_gnew)
{
    int i = blockIdx.x * blockDim.x + threadIdx.x;
    if (i >= BU) return;
    int  b  = i / UU;
    bool gm = click[b] >= 0.5f;
    float f  = sigm(pre[0ULL * BU + i]);
    float ii = sigm(pre[1ULL * BU + i]);
    float o  = sigm(pre[2ULL * BU + i]);
    float g  = tanhf(pre[3ULL * BU + i]);
    float sv = s_v[i];
    float svn = gm ? (f * sv + ii * g) : sv;
    out_svn[i]  = svn;
    out_hvn[i]  = gm ? (o * tanhf(svn)) : h_v[i];
    out_gnew[i] = gm ? 1.f : 0.f;
}

// Final MLP layer: out[b] = sigmoid(dot(M1[b,:64], Wf) + bf) (* scale[b])
// one warp per row
__global__ void mlp_final_k(const float* __restrict__ M1,
                            const float* __restrict__ Wf,
                            const float* __restrict__ bf,
                            const float* __restrict__ scale,  // nullable
                            float* __restrict__ out)
{
    int warp = (blockIdx.x * blockDim.x + threadIdx.x) >> 5;
    int lane = threadIdx.x & 31;
    if (warp >= BATCH) return;
    const float* r = M1 + (size_t)warp * P1;
    float s = r[lane] * Wf[lane] + r[lane + 32] * Wf[lane + 32];
#pragma unroll
    for (int o = 16; o; o >>= 1) s += __shfl_down_sync(0xffffffffu, s, o);
    if (lane == 0) {
        float v = sigm(s + bf[0]);
        if (scale) v *= scale[warp];
        out[warp] = v;
    }
}

// ---------------------------------------------------------------------------
// Launcher
// ---------------------------------------------------------------------------
extern "C" void kernel_launch(void* const* d_in, const int* in_sizes, int n_in,
                              void* d_out, int out_size)
{
    (void)in_sizes; (void)n_in; (void)out_size;

    const float* x        = (const float*)d_in[0];
    const float* click    = (const float*)d_in[1];
    const float* h_c      = (const float*)d_in[2];
    const float* h_v      = (const float*)d_in[3];
    const float* s_c      = (const float*)d_in[4];
    const float* s_v      = (const float*)d_in[5];
    const int*   g_prev   = (const int*)  d_in[6];
    const float* Wx_c     = (const float*)d_in[7];
    const float* bx_c     = (const float*)d_in[8];
    const float* Wh_c     = (const float*)d_in[9];
    const float* Wx_v     = (const float*)d_in[10];
    const float* bx_v     = (const float*)d_in[11];
    const float* Wh_v     = (const float*)d_in[12];
    const float* W_schat_c= (const float*)d_in[13];
    const float* W_schat_v= (const float*)d_in[14];
    const float* W_svhat_v= (const float*)d_in[15];
    const float* W_svhat_c= (const float*)d_in[16];
    const float* Wpc0     = (const float*)d_in[17];
    const float* bpc0     = (const float*)d_in[18];
    const float* Wpc1     = (const float*)d_in[19];
    const float* bpc1     = (const float*)d_in[20];
    const float* Wfcc     = (const float*)d_in[21];
    const float* bfcc     = (const float*)d_in[22];
    const float* Wpv0     = (const float*)d_in[23];
    const float* bpv0     = (const float*)d_in[24];
    const float* Wpv1     = (const float*)d_in[25];
    const float* bpv1     = (const float*)d_in[26];
    const float* Wfcv     = (const float*)d_in[27];
    const float* bfcv     = (const float*)d_in[28];

    float *pre_c, *pre_v, *t0, *t1, *t2, *t3, *schat, *svhat, *m0, *m1;
    cudaGetSymbolAddress((void**)&pre_c, g_pre_c);
    cudaGetSymbolAddress((void**)&pre_v, g_pre_v);
    cudaGetSymbolAddress((void**)&t0,    g_t0);
    cudaGetSymbolAddress((void**)&t1,    g_t1);
    cudaGetSymbolAddress((void**)&t2,    g_t2);
    cudaGetSymbolAddress((void**)&t3,    g_t3);
    cudaGetSymbolAddress((void**)&schat, g_schat);
    cudaGetSymbolAddress((void**)&svhat, g_svhat);
    cudaGetSymbolAddress((void**)&m0,    g_m0);
    cudaGetSymbolAddress((void**)&m1,    g_m1);

    float* out     = (float*)d_out;
    float* o_hcp   = out;                       // [B,1]
    float* o_hvp   = out + BATCH;               // [B,1]
    float* o_hcn   = out + 2 * BATCH;           // [B,U]
    float* o_hvn   = o_hcn + (size_t)BU;        // [B,U]
    float* o_scn   = o_hvn + (size_t)BU;        // [B,U]
    float* o_svn   = o_scn + (size_t)BU;        // [B,U]
    float* o_gnew  = o_svn + (size_t)BU;        // [B,U]

    dim3 blk(256);
    dim3 g256(UU / BN, BATCH / BM);      // N=256 -> (2, 256)
    dim3 g128(1, BATCH / BM);            // N=128
    dim3 g64 (1, BATCH / BM);            // N=64
    int  ewGrid = (BU + 255) / 256;

    // ---- Stage A: x-gates pre-activations + independent h-projections ----
    for (int k = 0; k < 4; k++) {
        sgemm_k<<<g256, blk>>>(x, Wx_c + (size_t)k * DD * UU, bx_c + k * UU,
                               nullptr, pre_c + (size_t)k * BU, UU, DD, 0);
        sgemm_k<<<g256, blk>>>(x, Wx_v + (size_t)k * DD * UU, bx_v + k * UU,
                               nullptr, pre_v + (size_t)k * BU, UU, DD, 0);
    }
    sgemm_k<<<g256, blk>>>(h_c, W_schat_c, nullptr, nullptr, t0, UU, UU, 0);
    sgemm_k<<<g256, blk>>>(h_v, W_schat_v, nullptr, nullptr, t1, UU, UU, 0);
    sgemm_k<<<g256, blk>>>(h_v, W_svhat_v, nullptr, nullptr, t2, UU, UU, 0);

    // ---- Stage B: select s_c_hat ----
    select_schat_k<<<ewGrid, blk>>>(g_prev, t0, t1, schat);

    // ---- Stage C: h-gates for click branch (accumulate into pre_c) ----
    for (int k = 0; k < 4; k++)
        sgemm_k<<<g256, blk>>>(schat, Wh_c + (size_t)k * UU * UU, nullptr,
                               pre_c + (size_t)k * BU, pre_c + (size_t)k * BU,
                               UU, UU, 0);

    // ---- Stage D: click gates -> s_c_n, h_c_n ----
    gates_c_k<<<ewGrid, blk>>>(pre_c, s_c, g_prev, o_scn, o_hcn);

    // ---- Stage E: click MLP ----
    sgemm_k<<<g128, blk>>>(o_hcn, Wpc0, bpc0, nullptr, m0, P0, UU, 1);
    sgemm_k<<<g64,  blk>>>(m0,    Wpc1, bpc1, nullptr, m1, P1, P0, 1);
    mlp_final_k<<<(BATCH * 32 + 255) / 256, blk>>>(m1, Wfcc, bfcc, nullptr, o_hcp);

    // ---- Stage F: s_v_hat ----
    sgemm_k<<<g256, blk>>>(o_hcn, W_svhat_c, nullptr, nullptr, t3, UU, UU, 0);
    svhat_k<<<ewGrid, blk>>>(click, t2, t3, svhat);

    // ---- Stage G: h-gates for conversion branch ----
    for (int k = 0; k < 4; k++)
        sgemm_k<<<g256, blk>>>(svhat, Wh_v + (size_t)k * UU * UU, nullptr,
                               pre_v + (size_t)k * BU, pre_v + (size_t)k * BU,
                               UU, UU, 0);

    // ---- Stage H: conversion gates -> s_v_n, h_v_n, g_new ----
    gates_v_k<<<ewGrid, blk>>>(pre_v, s_v, h_v, click, o_svn, o_hvn, o_gnew);

    // ---- Stage I: conversion MLP (scaled by h_c_p) ----
    sgemm_k<<<g128, blk>>>(o_hvn, Wpv0, bpv0, nullptr, m0, P0, UU, 1);
    sgemm_k<<<g64,  blk>>>(m0,    Wpv1, bpv1, nullptr, m1, P1, P0, 1);
    mlp_final_k<<<(BATCH * 32 + 255) / 256, blk>>>(m1, Wfcv, bfcv, o_hcp, o_hvp);
}